// round 12
// baseline (speedup 1.0000x reference)
#include <cuda_runtime.h>
#include <cuda_bf16.h>

// MyStrategicModel: per-sample CCP fixed point + projected gradient ascent.
// B = 524288, XDIM = 2. One thread per sample, all state in registers.
//
// Structure = R7/R9/R10/R11 (proven): adaptive CCP loop, warp-uniform epsilon
// exit on the fcoef fixed point. (R8's Aitken extrapolation failed 5.8e-2:
// never extrapolate across unconverged fixed-point map evaluations. The
// eps-exit is fail-safe: inner under-convergence only delays the exit.)
//
// Inner solve: projected gradient, two-mode optimal step
//   LR* = 2/(mu + Lbar), mu = 0.05, Lbar = 0.05 + 0.5|w|^2
// (LR* * L < 2 for all h' in [0,1] -> unconditionally stable; nonexpansive
// projection; unique maximizer identical to the reference's LR=1 iteration).
//
// R12: empirical transfer rel_err ~= 2 * eps_fc (R7/R9/R11). Raise eps_fc
// 8e-6 -> 2e-5 to exit one CCP round earlier (geometric gap, ratio ~0.3-0.5);
// trim final tail to 4 fast + 3 settle and cold round to 7 fast. Warm-round
// depth (5 fast) is frozen: it keeps inner residual below the exit's noise
// floor.
//
// Step (LR): x' = clip( (1-0.05LR)x + 0.05LR*r + LR*(fcoef-gcoef)*w
//                       - 0.475LR*pos*v ),  pos = (x.v - r.v > 0)
//   gcoef = 0.5*s*rsqrt(s^2+1), s = x.w + (b-1)
//   fcoef = 0.5*t*rsqrt(t^2+1), t = xt.w + (b+1)  (per CCP round)
// Folds: D = 1-0.05LR; c_a = 0.05LR*r; c_b = c_a - 0.475LR*v;
//   (fcoef-gcoef)*w = A*wh, A = s*rs + mfc2, mfc2 = -t*rsqrt(t^2+1) = -2*fcoef,
//   wh = -LR/2*w.  Convergence vote runs directly on mfc2 (threshold 2*eps_fc).

#define XLO (-10.0f)
#define XHI (10.0f)
#define CCP_EPS2 4e-5f    // = 2 * eps_fc, eps_fc = 2e-5, applied to mfc2

__device__ __forceinline__ float clampx(float x) {
    return fminf(fmaxf(x, XLO), XHI);
}

__global__ void __launch_bounds__(256)
strat_ccp_kernel(const float* __restrict__ X,
                 const float* __restrict__ W,
                 const float* __restrict__ Bp,
                 const float* __restrict__ V,
                 float* __restrict__ out, int B)
{
    int i = blockIdx.x * blockDim.x + threadIdx.x;
    if (i >= B) return;

    const float w0 = W[0], w1 = W[1];
    const float b  = Bp[0];
    const float v0 = V[0], v1 = V[1];

    const float2 r2 = reinterpret_cast<const float2*>(X)[i];
    const float r0 = r2.x, r1 = r2.y;

    // Optimal two-mode learning rate (runtime constant, uniform across lanes).
    const float Lbar = fmaf(0.5f, fmaf(w0, w0, w1 * w1), 0.05f);
    const float LRf  = 2.0f / (0.05f + Lbar);

    // Shared-by-step constants
    const float bm  = b - 1.0f;
    const float bp  = b + 1.0f;
    const float mrv = -fmaf(r1, v1, r0 * v0);        // -(r.v)

    // LR=1 (settle) constant set — used only in the final tail.
    const float wa0 = -0.5f * w0,        wa1 = -0.5f * w1;
    const float a0a = 0.05f * r0,        a1a = 0.05f * r1;
    const float a0b = a0a - 0.475f * v0, a1b = a1a - 0.475f * v1;

    // LR=LRf (fast) constant set
    const float wb0 = -0.5f * LRf * w0,  wb1 = -0.5f * LRf * w1;
    const float b0a = 0.05f * LRf * r0,  b1a = 0.05f * LRf * r1;
    const float b0b = b0a - 0.475f * LRf * v0;
    const float b1b = b1a - 0.475f * LRf * v1;
    const float Df  = 1.0f - 0.05f * LRf;

    const float x00 = clampx(r0);
    const float x01 = clampx(r1);

    float xt0 = r0, xt1 = r1;                        // CCP state
    float x0, x1, mfc2;                              // mfc2 = -2*fcoef

#define STEP(DEC, C0A, C1A, C0B, C1B, WH0, WH1) do {                  \
        float s  = fmaf(x0, w0, fmaf(x1, w1, bm));                    \
        float rs = rsqrtf(fmaf(s, s, 1.0f));                          \
        float A  = fmaf(s, rs, mfc2);                                 \
        float dv = fmaf(x1, v1, fmaf(x0, v0, mrv));                   \
        bool  p  = dv > 0.0f;                                         \
        float c0 = p ? C0B : C0A;                                     \
        float c1 = p ? C1B : C1A;                                     \
        x0 = clampx(fmaf(A, WH0, fmaf(DEC, x0, c0)));                 \
        x1 = clampx(fmaf(A, WH1, fmaf(DEC, x1, c1)));                 \
    } while (0)

#define STEPF() STEP(Df, b0a, b1a, b0b, b1b, wb0, wb1)
#define STEP1() STEP(0.95f, a0a, a1a, a0b, a1b, wa0, wa1)

    // mfc2 = -t*rsqrt(t^2+1) from current xt (== -2*fcoef).
#define MFC2_FROM_XT() do {                                           \
        float t  = fmaf(xt0, w0, fmaf(xt1, w1, bp));                  \
        float rt = rsqrtf(fmaf(t, t, 1.0f));                          \
        mfc2 = -t * rt;                                               \
    } while (0)

    float mprev;

    // Round 1: cold start. 7 fast steps.
    MFC2_FROM_XT();
    mprev = mfc2;
    x0 = x00; x1 = x01;
    #pragma unroll
    for (int k = 0; k < 7; ++k) { STEPF(); }
    xt0 = x0; xt1 = x1;

    // Rounds 2..11: warm start, 5 fast steps; warp-uniform mfc2 exit.
    #pragma unroll 1
    for (int c = 1; c < 11; ++c) {
        MFC2_FROM_XT();
        if (__all_sync(0xffffffffu, fabsf(mfc2 - mprev) <= CCP_EPS2)) break;
        mprev = mfc2;
        x0 = xt0; x1 = xt1;
        #pragma unroll
        for (int k = 0; k < 5; ++k) { STEPF(); }
        xt0 = x0; xt1 = x1;
    }

    // Final solve at CCP fixed-point fcoef: short polish, reference-regime
    // tail. 4 fast + 3 settle.
    MFC2_FROM_XT();
    x0 = xt0; x1 = xt1;
    #pragma unroll
    for (int k = 0; k < 4; ++k) { STEPF(); }
    #pragma unroll
    for (int k = 0; k < 3; ++k) { STEP1(); }
#undef STEP
#undef STEPF
#undef STEP1
#undef MFC2_FROM_XT

    out[i] = fmaf(x0, w0, fmaf(x1, w1, b));
}

extern "C" void kernel_launch(void* const* d_in, const int* in_sizes, int n_in,
                              void* d_out, int out_size)
{
    const float* X = (const float*)d_in[0];   // [B, 2]
    const float* W = (const float*)d_in[1];   // [2]
    const float* B = (const float*)d_in[2];   // [1]
    const float* V = (const float*)d_in[3];   // [2]
    float* out = (float*)d_out;               // [B]

    int nB = in_sizes[0] / 2;
    int threads = 256;
    int blocks = (nB + threads - 1) / threads;
    strat_ccp_kernel<<<blocks, threads>>>(X, W, B, V, out, nB);
}

// round 13
// speedup vs baseline: 1.3735x; 1.3735x over previous
#include <cuda_runtime.h>
#include <cuda_bf16.h>

// MyStrategicModel: per-sample CCP fixed point + projected gradient ascent.
// B = 524288, XDIM = 2. One thread per sample, all state in registers.
//
// Structure = R11 (best proven 22.0us): adaptive CCP loop, warp-uniform
// epsilon exit on the fcoef fixed point.
// Failure log: R8 Aitken extrapolation -> 5.8e-2 (never extrapolate across
// unconverged map evaluations). R12 cold-round trim 8f->7f -> +7us (cold
// inner residual feeds the exit's noise floor and delays the warp vote;
// cold/warm round DEPTHS are load-bearing, frozen at 8f/5f).
//
// R13 deltas vs R11 (causally clean): eps2 1.6e-5 -> 4e-5 (same fc sequence,
// exit strictly same-or-earlier; error cost measured ~1.8e-5 in R12) and
// final tail 4f+4s -> 4f+3s (loop-independent).
//
// Inner solve: projected gradient, two-mode optimal step
//   LR* = 2/(mu + Lbar), mu = 0.05, Lbar = 0.05 + 0.5|w|^2
// (LR* * L < 2 for all h' in [0,1] -> unconditionally stable; nonexpansive
// projection; unique maximizer identical to the reference's LR=1 iteration).
//
// Step (LR): x' = clip( (1-0.05LR)x + 0.05LR*r + LR*(fcoef-gcoef)*w
//                       - 0.475LR*pos*v ),  pos = (x.v - r.v > 0)
//   gcoef = 0.5*s*rsqrt(s^2+1), s = x.w + (b-1)
//   fcoef = 0.5*t*rsqrt(t^2+1), t = xt.w + (b+1)  (per CCP round)
// Folds: D = 1-0.05LR; c_a = 0.05LR*r; c_b = c_a - 0.475LR*v;
//   (fcoef-gcoef)*w = A*wh, A = s*rs + mfc2, mfc2 = -t*rsqrt(t^2+1) = -2*fcoef,
//   wh = -LR/2*w.  Convergence vote runs directly on mfc2.

#define XLO (-10.0f)
#define XHI (10.0f)
#define CCP_EPS2 4e-5f    // on mfc2 = -2*fc  (eps_fc = 2e-5)

__device__ __forceinline__ float clampx(float x) {
    return fminf(fmaxf(x, XLO), XHI);
}

__global__ void __launch_bounds__(256)
strat_ccp_kernel(const float* __restrict__ X,
                 const float* __restrict__ W,
                 const float* __restrict__ Bp,
                 const float* __restrict__ V,
                 float* __restrict__ out, int B)
{
    int i = blockIdx.x * blockDim.x + threadIdx.x;
    if (i >= B) return;

    const float w0 = W[0], w1 = W[1];
    const float b  = Bp[0];
    const float v0 = V[0], v1 = V[1];

    const float2 r2 = reinterpret_cast<const float2*>(X)[i];
    const float r0 = r2.x, r1 = r2.y;

    // Optimal two-mode learning rate (runtime constant, uniform across lanes).
    const float Lbar = fmaf(0.5f, fmaf(w0, w0, w1 * w1), 0.05f);
    const float LRf  = 2.0f / (0.05f + Lbar);

    // Shared-by-step constants
    const float bm  = b - 1.0f;
    const float bp  = b + 1.0f;
    const float mrv = -fmaf(r1, v1, r0 * v0);        // -(r.v)

    // LR=1 (settle) constant set — used only in the final tail.
    const float wa0 = -0.5f * w0,        wa1 = -0.5f * w1;
    const float a0a = 0.05f * r0,        a1a = 0.05f * r1;
    const float a0b = a0a - 0.475f * v0, a1b = a1a - 0.475f * v1;

    // LR=LRf (fast) constant set
    const float wb0 = -0.5f * LRf * w0,  wb1 = -0.5f * LRf * w1;
    const float b0a = 0.05f * LRf * r0,  b1a = 0.05f * LRf * r1;
    const float b0b = b0a - 0.475f * LRf * v0;
    const float b1b = b1a - 0.475f * LRf * v1;
    const float Df  = 1.0f - 0.05f * LRf;

    const float x00 = clampx(r0);
    const float x01 = clampx(r1);

    float xt0 = r0, xt1 = r1;                        // CCP state
    float x0, x1, mfc2;                              // mfc2 = -2*fcoef

#define STEP(DEC, C0A, C1A, C0B, C1B, WH0, WH1) do {                  \
        float s  = fmaf(x0, w0, fmaf(x1, w1, bm));                    \
        float rs = rsqrtf(fmaf(s, s, 1.0f));                          \
        float A  = fmaf(s, rs, mfc2);                                 \
        float dv = fmaf(x1, v1, fmaf(x0, v0, mrv));                   \
        bool  p  = dv > 0.0f;                                         \
        float c0 = p ? C0B : C0A;                                     \
        float c1 = p ? C1B : C1A;                                     \
        x0 = clampx(fmaf(A, WH0, fmaf(DEC, x0, c0)));                 \
        x1 = clampx(fmaf(A, WH1, fmaf(DEC, x1, c1)));                 \
    } while (0)

#define STEPF() STEP(Df, b0a, b1a, b0b, b1b, wb0, wb1)
#define STEP1() STEP(0.95f, a0a, a1a, a0b, a1b, wa0, wa1)

    // mfc2 = -t*rsqrt(t^2+1) from current xt (== -2*fcoef).
#define MFC2_FROM_XT() do {                                           \
        float t  = fmaf(xt0, w0, fmaf(xt1, w1, bp));                  \
        float rt = rsqrtf(fmaf(t, t, 1.0f));                          \
        mfc2 = -t * rt;                                               \
    } while (0)

    float mprev;

    // Round 1: cold start. 8 fast steps (depth frozen — R12 lesson).
    MFC2_FROM_XT();
    mprev = mfc2;
    x0 = x00; x1 = x01;
    #pragma unroll
    for (int k = 0; k < 8; ++k) { STEPF(); }
    xt0 = x0; xt1 = x1;

    // Rounds 2..11: warm start, 5 fast steps; warp-uniform mfc2 exit.
    #pragma unroll 1
    for (int c = 1; c < 11; ++c) {
        MFC2_FROM_XT();
        if (__all_sync(0xffffffffu, fabsf(mfc2 - mprev) <= CCP_EPS2)) break;
        mprev = mfc2;
        x0 = xt0; x1 = xt1;
        #pragma unroll
        for (int k = 0; k < 5; ++k) { STEPF(); }
        xt0 = x0; xt1 = x1;
    }

    // Final solve at CCP fixed-point fcoef: short polish, reference-regime
    // tail. 4 fast + 3 settle.
    MFC2_FROM_XT();
    x0 = xt0; x1 = xt1;
    #pragma unroll
    for (int k = 0; k < 4; ++k) { STEPF(); }
    #pragma unroll
    for (int k = 0; k < 3; ++k) { STEP1(); }
#undef STEP
#undef STEPF
#undef STEP1
#undef MFC2_FROM_XT

    out[i] = fmaf(x0, w0, fmaf(x1, w1, b));
}

extern "C" void kernel_launch(void* const* d_in, const int* in_sizes, int n_in,
                              void* d_out, int out_size)
{
    const float* X = (const float*)d_in[0];   // [B, 2]
    const float* W = (const float*)d_in[1];   // [2]
    const float* B = (const float*)d_in[2];   // [1]
    const float* V = (const float*)d_in[3];   // [2]
    float* out = (float*)d_out;               // [B]

    int nB = in_sizes[0] / 2;
    int threads = 256;
    int blocks = (nB + threads - 1) / threads;
    strat_ccp_kernel<<<blocks, threads>>>(X, W, B, V, out, nB);
}

// round 16
// speedup vs baseline: 1.3924x; 1.0137x over previous
#include <cuda_runtime.h>
#include <cuda_bf16.h>

// MyStrategicModel: per-sample CCP fixed point + projected gradient ascent.
// B = 524288, XDIM = 2. One thread per sample, all state in registers.
//
// Numerics = R13 exactly (proven 21.2us, rel_err 1.67e-5): adaptive CCP loop
// (up to 11 rounds), warp-uniform epsilon exit on the fcoef fixed point,
// cold 8f, warm 5f, final 4f+3s, eps2 = 4e-5.
//
// Failure log:
//   R8  Aitken extrapolation -> 5.8e-2. Never extrapolate across unconverged
//       fixed-point map evaluations.
//   R12 cold 8f->7f -> +7us. Inner residual feeds the exit's noise floor;
//       cold/warm depths are load-bearing (frozen 8f/5f).
//   R14 round cap 11->8 -> rel_err 1.3e-3. rel_err is max-type; the warps
//       still above eps at round 8 are the correctness-critical ones. NEVER
//       bound the adaptive loop below what the eps-criterion demands.
//   R15 infra failure (container), no data — this is the same kernel resubmitted.
//
// Single delta vs R13: 128-thread blocks (numerically inert) — finer
// scheduling granularity for the ragged last wave caused by variable
// per-warp CCP round counts.
//
// Inner solve: projected gradient, two-mode optimal step
//   LR* = 2/(mu + Lbar), mu = 0.05, Lbar = 0.05 + 0.5|w|^2
// (LR* * L < 2 for all h' in [0,1] -> unconditionally stable; nonexpansive
// projection; unique maximizer identical to the reference's LR=1 iteration).
//
// Step (LR): x' = clip( (1-0.05LR)x + 0.05LR*r + LR*(fcoef-gcoef)*w
//                       - 0.475LR*pos*v ),  pos = (x.v - r.v > 0)
//   gcoef = 0.5*s*rsqrt(s^2+1), s = x.w + (b-1)
//   fcoef = 0.5*t*rsqrt(t^2+1), t = xt.w + (b+1)  (per CCP round)
// Folds: D = 1-0.05LR; c_a = 0.05LR*r; c_b = c_a - 0.475LR*v;
//   (fcoef-gcoef)*w = A*wh, A = s*rs + mfc2, mfc2 = -t*rsqrt(t^2+1) = -2*fcoef,
//   wh = -LR/2*w.  Convergence vote runs directly on mfc2.

#define XLO (-10.0f)
#define XHI (10.0f)
#define CCP_EPS2 4e-5f    // on mfc2 = -2*fc  (eps_fc = 2e-5)

__device__ __forceinline__ float clampx(float x) {
    return fminf(fmaxf(x, XLO), XHI);
}

__global__ void __launch_bounds__(128)
strat_ccp_kernel(const float* __restrict__ X,
                 const float* __restrict__ W,
                 const float* __restrict__ Bp,
                 const float* __restrict__ V,
                 float* __restrict__ out, int B)
{
    int i = blockIdx.x * blockDim.x + threadIdx.x;
    if (i >= B) return;

    const float w0 = W[0], w1 = W[1];
    const float b  = Bp[0];
    const float v0 = V[0], v1 = V[1];

    const float2 r2 = reinterpret_cast<const float2*>(X)[i];
    const float r0 = r2.x, r1 = r2.y;

    // Optimal two-mode learning rate (runtime constant, uniform across lanes).
    const float Lbar = fmaf(0.5f, fmaf(w0, w0, w1 * w1), 0.05f);
    const float LRf  = 2.0f / (0.05f + Lbar);

    // Shared-by-step constants
    const float bm  = b - 1.0f;
    const float bp  = b + 1.0f;
    const float mrv = -fmaf(r1, v1, r0 * v0);        // -(r.v)

    // LR=1 (settle) constant set — used only in the final tail.
    const float wa0 = -0.5f * w0,        wa1 = -0.5f * w1;
    const float a0a = 0.05f * r0,        a1a = 0.05f * r1;
    const float a0b = a0a - 0.475f * v0, a1b = a1a - 0.475f * v1;

    // LR=LRf (fast) constant set
    const float wb0 = -0.5f * LRf * w0,  wb1 = -0.5f * LRf * w1;
    const float b0a = 0.05f * LRf * r0,  b1a = 0.05f * LRf * r1;
    const float b0b = b0a - 0.475f * LRf * v0;
    const float b1b = b1a - 0.475f * LRf * v1;
    const float Df  = 1.0f - 0.05f * LRf;

    const float x00 = clampx(r0);
    const float x01 = clampx(r1);

    float xt0 = r0, xt1 = r1;                        // CCP state
    float x0, x1, mfc2;                              // mfc2 = -2*fcoef

#define STEP(DEC, C0A, C1A, C0B, C1B, WH0, WH1) do {                  \
        float s  = fmaf(x0, w0, fmaf(x1, w1, bm));                    \
        float rs = rsqrtf(fmaf(s, s, 1.0f));                          \
        float A  = fmaf(s, rs, mfc2);                                 \
        float dv = fmaf(x1, v1, fmaf(x0, v0, mrv));                   \
        bool  p  = dv > 0.0f;                                         \
        float c0 = p ? C0B : C0A;                                     \
        float c1 = p ? C1B : C1A;                                     \
        x0 = clampx(fmaf(A, WH0, fmaf(DEC, x0, c0)));                 \
        x1 = clampx(fmaf(A, WH1, fmaf(DEC, x1, c1)));                 \
    } while (0)

#define STEPF() STEP(Df, b0a, b1a, b0b, b1b, wb0, wb1)
#define STEP1() STEP(0.95f, a0a, a1a, a0b, a1b, wa0, wa1)

    // mfc2 = -t*rsqrt(t^2+1) from current xt (== -2*fcoef).
#define MFC2_FROM_XT() do {                                           \
        float t  = fmaf(xt0, w0, fmaf(xt1, w1, bp));                  \
        float rt = rsqrtf(fmaf(t, t, 1.0f));                          \
        mfc2 = -t * rt;                                               \
    } while (0)

    float mprev;

    // Round 1: cold start. 8 fast steps (depth frozen — R12 lesson).
    MFC2_FROM_XT();
    mprev = mfc2;
    x0 = x00; x1 = x01;
    #pragma unroll
    for (int k = 0; k < 8; ++k) { STEPF(); }
    xt0 = x0; xt1 = x1;

    // Rounds 2..11: warm start, 5 fast steps; warp-uniform mfc2 exit.
    // Full 11-round bound — R14 lesson: the slow warps are correctness-critical.
    #pragma unroll 1
    for (int c = 1; c < 11; ++c) {
        MFC2_FROM_XT();
        if (__all_sync(0xffffffffu, fabsf(mfc2 - mprev) <= CCP_EPS2)) break;
        mprev = mfc2;
        x0 = xt0; x1 = xt1;
        #pragma unroll
        for (int k = 0; k < 5; ++k) { STEPF(); }
        xt0 = x0; xt1 = x1;
    }

    // Final solve at CCP fixed-point fcoef: short polish, reference-regime
    // tail. 4 fast + 3 settle (R13-proven).
    MFC2_FROM_XT();
    x0 = xt0; x1 = xt1;
    #pragma unroll
    for (int k = 0; k < 4; ++k) { STEPF(); }
    #pragma unroll
    for (int k = 0; k < 3; ++k) { STEP1(); }
#undef STEP
#undef STEPF
#undef STEP1
#undef MFC2_FROM_XT

    out[i] = fmaf(x0, w0, fmaf(x1, w1, b));
}

extern "C" void kernel_launch(void* const* d_in, const int* in_sizes, int n_in,
                              void* d_out, int out_size)
{
    const float* X = (const float*)d_in[0];   // [B, 2]
    const float* W = (const float*)d_in[1];   // [2]
    const float* B = (const float*)d_in[2];   // [1]
    const float* V = (const float*)d_in[3];   // [2]
    float* out = (float*)d_out;               // [B]

    int nB = in_sizes[0] / 2;
    int threads = 128;
    int blocks = (nB + threads - 1) / threads;
    strat_ccp_kernel<<<blocks, threads>>>(X, W, B, V, out, nB);
}

// round 17
// speedup vs baseline: 1.5405x; 1.1064x over previous
#include <cuda_runtime.h>
#include <cuda_bf16.h>

// MyStrategicModel: per-sample CCP fixed point + projected gradient ascent.
// B = 524288, XDIM = 2. One thread per sample, all state in registers.
//
// Base = R16 (proven 21.0us, rel_err 1.6749e-5, bit-stable across two runs):
// adaptive CCP loop (up to 11 rounds), warp-uniform epsilon exit on fcoef,
// cold 8f, warm 5f, eps2 = 4e-5, 128-thread blocks.
//
// Failure log:
//   R8  Aitken extrapolation -> 5.8e-2. Never extrapolate across unconverged
//       fixed-point map evaluations.
//   R12 cold 8f->7f -> +7us. Inner residual feeds the exit's noise floor;
//       cold/warm depths are load-bearing (frozen 8f/5f).
//   R14 round cap 11->8 -> rel_err 1.3e-3. rel_err is max-type; warps still
//       above eps at round 8 are correctness-critical. Never bound the
//       adaptive loop below what the eps-criterion demands.
//
// R17 single delta: the LR=1 "settle" regime is deleted. It guarded a hinge
// limit-cycle pathology disproven in R11 (no chatter signature in this data).
// With no chatter, LR1 polishing (rate 0.95/step) is strictly dominated by
// LRf polishing (rate ~0.46/step): final tail 4f+3s -> 4f is both shorter
// AND contracts an eps-scale residual at least as much. Also drops the LR1
// constant set (lower reg pressure).
//
// Inner solve: projected gradient, two-mode optimal step
//   LR* = 2/(mu + Lbar), mu = 0.05, Lbar = 0.05 + 0.5|w|^2
// (LR* * L < 2 for all h' in [0,1] -> unconditionally stable; nonexpansive
// projection; unique maximizer identical to the reference's LR=1 iteration).
//
// Step: x' = clip( (1-0.05LR)x + 0.05LR*r + LR*(fcoef-gcoef)*w
//                  - 0.475LR*pos*v ),  pos = (x.v - r.v > 0)
//   gcoef = 0.5*s*rsqrt(s^2+1), s = x.w + (b-1)
//   fcoef = 0.5*t*rsqrt(t^2+1), t = xt.w + (b+1)  (per CCP round)
// Folds: D = 1-0.05LR; c_a = 0.05LR*r; c_b = c_a - 0.475LR*v;
//   (fcoef-gcoef)*w = A*wh, A = s*rs + mfc2, mfc2 = -t*rsqrt(t^2+1) = -2*fcoef,
//   wh = -LR/2*w.  Convergence vote runs directly on mfc2.

#define XLO (-10.0f)
#define XHI (10.0f)
#define CCP_EPS2 4e-5f    // on mfc2 = -2*fc  (eps_fc = 2e-5)

__device__ __forceinline__ float clampx(float x) {
    return fminf(fmaxf(x, XLO), XHI);
}

__global__ void __launch_bounds__(128)
strat_ccp_kernel(const float* __restrict__ X,
                 const float* __restrict__ W,
                 const float* __restrict__ Bp,
                 const float* __restrict__ V,
                 float* __restrict__ out, int B)
{
    int i = blockIdx.x * blockDim.x + threadIdx.x;
    if (i >= B) return;

    const float w0 = W[0], w1 = W[1];
    const float b  = Bp[0];
    const float v0 = V[0], v1 = V[1];

    const float2 r2 = reinterpret_cast<const float2*>(X)[i];
    const float r0 = r2.x, r1 = r2.y;

    // Optimal two-mode learning rate (runtime constant, uniform across lanes).
    const float Lbar = fmaf(0.5f, fmaf(w0, w0, w1 * w1), 0.05f);
    const float LRf  = 2.0f / (0.05f + Lbar);

    // Shared-by-step constants
    const float bm  = b - 1.0f;
    const float bp  = b + 1.0f;
    const float mrv = -fmaf(r1, v1, r0 * v0);        // -(r.v)

    // Fast-step constant set (the only regime — settle regime deleted, R17)
    const float wb0 = -0.5f * LRf * w0,  wb1 = -0.5f * LRf * w1;
    const float b0a = 0.05f * LRf * r0,  b1a = 0.05f * LRf * r1;
    const float b0b = b0a - 0.475f * LRf * v0;
    const float b1b = b1a - 0.475f * LRf * v1;
    const float Df  = 1.0f - 0.05f * LRf;

    const float x00 = clampx(r0);
    const float x01 = clampx(r1);

    float xt0 = r0, xt1 = r1;                        // CCP state
    float x0, x1, mfc2;                              // mfc2 = -2*fcoef

#define STEPF() do {                                                  \
        float s  = fmaf(x0, w0, fmaf(x1, w1, bm));                    \
        float rs = rsqrtf(fmaf(s, s, 1.0f));                          \
        float A  = fmaf(s, rs, mfc2);                                 \
        float dv = fmaf(x1, v1, fmaf(x0, v0, mrv));                   \
        bool  p  = dv > 0.0f;                                         \
        float c0 = p ? b0b : b0a;                                     \
        float c1 = p ? b1b : b1a;                                     \
        x0 = clampx(fmaf(A, wb0, fmaf(Df, x0, c0)));                  \
        x1 = clampx(fmaf(A, wb1, fmaf(Df, x1, c1)));                  \
    } while (0)

    // mfc2 = -t*rsqrt(t^2+1) from current xt (== -2*fcoef).
#define MFC2_FROM_XT() do {                                           \
        float t  = fmaf(xt0, w0, fmaf(xt1, w1, bp));                  \
        float rt = rsqrtf(fmaf(t, t, 1.0f));                          \
        mfc2 = -t * rt;                                               \
    } while (0)

    float mprev;

    // Round 1: cold start. 8 fast steps (depth frozen — R12 lesson).
    MFC2_FROM_XT();
    mprev = mfc2;
    x0 = x00; x1 = x01;
    #pragma unroll
    for (int k = 0; k < 8; ++k) { STEPF(); }
    xt0 = x0; xt1 = x1;

    // Rounds 2..11: warm start, 5 fast steps; warp-uniform mfc2 exit.
    // Full 11-round bound — R14 lesson: slow warps are correctness-critical.
    #pragma unroll 1
    for (int c = 1; c < 11; ++c) {
        MFC2_FROM_XT();
        if (__all_sync(0xffffffffu, fabsf(mfc2 - mprev) <= CCP_EPS2)) break;
        mprev = mfc2;
        x0 = xt0; x1 = xt1;
        #pragma unroll
        for (int k = 0; k < 5; ++k) { STEPF(); }
        xt0 = x0; xt1 = x1;
    }

    // Final solve at CCP fixed-point fcoef: 4 fast steps (starts at its own
    // fixed point — R10; LRf polishes strictly faster than LR1 — R17).
    MFC2_FROM_XT();
    x0 = xt0; x1 = xt1;
    #pragma unroll
    for (int k = 0; k < 4; ++k) { STEPF(); }
#undef STEPF
#undef MFC2_FROM_XT

    out[i] = fmaf(x0, w0, fmaf(x1, w1, b));
}

extern "C" void kernel_launch(void* const* d_in, const int* in_sizes, int n_in,
                              void* d_out, int out_size)
{
    const float* X = (const float*)d_in[0];   // [B, 2]
    const float* W = (const float*)d_in[1];   // [2]
    const float* B = (const float*)d_in[2];   // [1]
    const float* V = (const float*)d_in[3];   // [2]
    float* out = (float*)d_out;               // [B]

    int nB = in_sizes[0] / 2;
    int threads = 128;
    int blocks = (nB + threads - 1) / threads;
    strat_ccp_kernel<<<blocks, threads>>>(X, W, B, V, out, nB);
}